// round 7
// baseline (speedup 1.0000x reference)
#include <cuda_runtime.h>
#include <cuda_bf16.h>
#include <cstdint>

#define NMAX 100000
#define EMAX 1600000
#define ETOTMAX (NMAX + EMAX)
#define GMAX 256
#define HEADS 4
#define SCAN_BLK 512

// ---------------- scratch (device globals; no allocation allowed) -------------
__device__ float g_b0[NMAX * 128];
__device__ float g_b1[NMAX * 128];
__device__ float g_b2[NMAX * 128];
__device__ float g_dis[NMAX];
__device__ float g_asrc[NMAX * HEADS];
__device__ float g_adst[NMAX * HEADS];
__device__ float g_bnsum[128];
__device__ float g_bnsq[128];
__device__ float g_scale[128];
__device__ float g_shift[128];
__device__ float g_pool[GMAX * 64];
__device__ float g_cnt[GMAX];
__device__ int   g_hist[NMAX];
__device__ int   g_off[NMAX + 1];
__device__ int   g_cur[NMAX];
__device__ int   g_csr_row[ETOTMAX];
__device__ float g_csr_nrm[ETOTMAX];
__device__ int   g_blksum[256];

// ---------------- helpers ----------------
__device__ __forceinline__ float lrelu(float v) { return v > 0.f ? v : 0.2f * v; }
static inline int cdiv(int a, int b) { return (a + b - 1) / b; }

// ---------------- CSR build ----------------
__global__ void fill_int_kernel(int* p, int v, int n) {
    int t = blockIdx.x * blockDim.x + threadIdx.x;
    if (t < n) p[t] = v;
}

__global__ void hist_kernel(const int* __restrict__ col, int* hist, int E) {
    int e = blockIdx.x * blockDim.x + threadIdx.x;
    if (e < E) atomicAdd(&hist[col[e]], 1);
}

__global__ void scan1_kernel(const int* __restrict__ hist, int* blksum, int Nn) {
    __shared__ int sm[SCAN_BLK];
    int i = blockIdx.x * SCAN_BLK + threadIdx.x;
    sm[threadIdx.x] = (i < Nn) ? hist[i] : 0;
    __syncthreads();
    for (int st = SCAN_BLK / 2; st > 0; st >>= 1) {
        if (threadIdx.x < st) sm[threadIdx.x] += sm[threadIdx.x + st];
        __syncthreads();
    }
    if (threadIdx.x == 0) blksum[blockIdx.x] = sm[0];
}

__global__ void scan2_kernel(int* blksum, int nb) {
    __shared__ int sm[256];
    int v = (threadIdx.x < nb) ? blksum[threadIdx.x] : 0;
    sm[threadIdx.x] = v;
    __syncthreads();
    for (int st = 1; st < 256; st <<= 1) {
        int t = (threadIdx.x >= st) ? sm[threadIdx.x - st] : 0;
        __syncthreads();
        sm[threadIdx.x] += t;
        __syncthreads();
    }
    if (threadIdx.x < nb) blksum[threadIdx.x] = sm[threadIdx.x] - v;  // exclusive
}

__global__ void scan3_kernel(const int* __restrict__ hist, const int* __restrict__ blksum,
                             int* off, int* cur, int* csr_row, float* csr_nrm,
                             float* dis, int Nn) {
    __shared__ int sm[SCAN_BLK];
    int i = blockIdx.x * SCAN_BLK + threadIdx.x;
    int v = (i < Nn) ? hist[i] : 0;
    sm[threadIdx.x] = v;
    __syncthreads();
    for (int st = 1; st < SCAN_BLK; st <<= 1) {
        int t = (threadIdx.x >= st) ? sm[threadIdx.x - st] : 0;
        __syncthreads();
        sm[threadIdx.x] += t;
        __syncthreads();
    }
    if (i < Nn) {
        int excl = sm[threadIdx.x] - v + blksum[blockIdx.x];
        off[i] = excl;
        cur[i] = excl + 1;              // slot excl reserved for self-loop
        dis[i] = rsqrtf((float)v);
        csr_row[excl] = i;
        csr_nrm[excl] = 1.0f / (float)v;
        if (i == Nn - 1) off[Nn] = excl + v;
    }
}

__global__ void scatter_kernel(const int* __restrict__ row, const int* __restrict__ col,
                               const float* __restrict__ dis, int* cur,
                               int* csr_row, float* csr_nrm, int E) {
    int e = blockIdx.x * blockDim.x + threadIdx.x;
    if (e >= E) return;
    int r = row[e], c = col[e];
    int pos = atomicAdd(&cur[c], 1);
    csr_row[pos] = r;
    csr_nrm[pos] = dis[r] * dis[c];
}

// ---------------- GEMM (double-buffered smem, register prefetch) ----------------
// C[M,N] = op(A)[M,K] @ B[K,N].  MODE: 0 = raw A, 1 = A*scl+shf, 2 = lrelu(A*scl+shf)
template <int BM, int BN, int MODE>
__global__ void __launch_bounds__(256) gemm_kernel(
    const float* __restrict__ A, const float* __restrict__ B, float* __restrict__ C,
    const float* __restrict__ scl, const float* __restrict__ shf, int M, int N, int K) {
    constexpr int TM = BM / 16, TN = BN / 16;
    constexpr int ALOADS = BM * 4 / 256;       // float4 A loads per thread per tile
    constexpr int BLOADS = BN * 16 / 4 / 256;  // float4 B loads per thread per tile
    __shared__ float As[2][16][BM + 4];
    __shared__ float Bs[2][16][BN];
    int tid = threadIdx.x;
    int tx = tid & 15, ty = tid >> 4;
    int rowBase = blockIdx.y * BM;
    int colBase = blockIdx.x * BN;

    float4 aReg[ALOADS], bReg[BLOADS];

    auto loadTile = [&](int k0) {
#pragma unroll
        for (int i = 0; i < ALOADS; i++) {
            int idx = tid + i * 256;
            int r = idx >> 2, q = idx & 3;
            int gr = rowBase + r;
            float4 v = make_float4(0.f, 0.f, 0.f, 0.f);
            if (gr < M) v = *(const float4*)&A[(size_t)gr * K + k0 + q * 4];
            if (MODE >= 1) {
                float4 s4 = *(const float4*)&scl[k0 + q * 4];
                float4 h4 = *(const float4*)&shf[k0 + q * 4];
                v.x = v.x * s4.x + h4.x; v.y = v.y * s4.y + h4.y;
                v.z = v.z * s4.z + h4.z; v.w = v.w * s4.w + h4.w;
                if (MODE == 2) { v.x = lrelu(v.x); v.y = lrelu(v.y); v.z = lrelu(v.z); v.w = lrelu(v.w); }
            }
            aReg[i] = v;
        }
#pragma unroll
        for (int i = 0; i < BLOADS; i++) {
            int idx = tid + i * 256;
            int r = idx / (BN / 4), c = idx % (BN / 4);
            bReg[i] = *(const float4*)&B[(size_t)(k0 + r) * N + colBase + c * 4];
        }
    };
    auto storeTile = [&](int buf) {
#pragma unroll
        for (int i = 0; i < ALOADS; i++) {
            int idx = tid + i * 256;
            int r = idx >> 2, q = idx & 3;
            As[buf][q * 4 + 0][r] = aReg[i].x; As[buf][q * 4 + 1][r] = aReg[i].y;
            As[buf][q * 4 + 2][r] = aReg[i].z; As[buf][q * 4 + 3][r] = aReg[i].w;
        }
#pragma unroll
        for (int i = 0; i < BLOADS; i++) {
            int idx = tid + i * 256;
            int r = idx / (BN / 4), c = idx % (BN / 4);
            *(float4*)&Bs[buf][r][c * 4] = bReg[i];
        }
    };

    float acc[TM][TN] = {};
    loadTile(0);
    storeTile(0);
    __syncthreads();
    int nT = K / 16;
    for (int t = 0; t < nT; t++) {
        int cur = t & 1, nxt = cur ^ 1;
        if (t + 1 < nT) loadTile((t + 1) * 16);
#pragma unroll
        for (int kk = 0; kk < 16; kk++) {
            float a[TM], b[TN];
#pragma unroll
            for (int m = 0; m < TM; m += 4)
                *(float4*)&a[m] = *(const float4*)&As[cur][kk][ty * TM + m];
#pragma unroll
            for (int n = 0; n < TN; n += 4)
                *(float4*)&b[n] = *(const float4*)&Bs[cur][kk][tx * TN + n];
#pragma unroll
            for (int m = 0; m < TM; m++)
#pragma unroll
                for (int n = 0; n < TN; n++) acc[m][n] += a[m] * b[n];
        }
        if (t + 1 < nT) {
            storeTile(nxt);
        }
        __syncthreads();
    }
#pragma unroll
    for (int m = 0; m < TM; m++) {
        int gr = rowBase + ty * TM + m;
        if (gr < M) {
#pragma unroll
            for (int n = 0; n < TN; n += 4) {
                float4 v = make_float4(acc[m][n], acc[m][n + 1], acc[m][n + 2], acc[m][n + 3]);
                *(float4*)&C[(size_t)gr * N + colBase + tx * TN + n] = v;
            }
        }
    }
}

// ---------------- GCN aggregation: warp per node, CSR gather, MLP=4 ----------------
template <int D>
__global__ void gcn_agg_csr_kernel(const float* __restrict__ h, const int* __restrict__ off,
                                   const int* __restrict__ csr_row,
                                   const float* __restrict__ csr_nrm,
                                   float* __restrict__ out, int Nn) {
    int node = (blockIdx.x * blockDim.x + threadIdx.x) >> 5;
    if (node >= Nn) return;
    int lane = threadIdx.x & 31;
    constexpr int V = D / 32;
    int s0 = off[node], s1 = off[node + 1];
    float acc[V] = {};
    int s = s0;
    for (; s + 4 <= s1; s += 4) {
        int r0 = csr_row[s + 0], r1 = csr_row[s + 1];
        int r2 = csr_row[s + 2], r3 = csr_row[s + 3];
        float n0 = csr_nrm[s + 0], n1 = csr_nrm[s + 1];
        float n2 = csr_nrm[s + 2], n3 = csr_nrm[s + 3];
        if (V == 4) {
            float4 v0 = *(const float4*)(h + (size_t)r0 * D + lane * 4);
            float4 v1 = *(const float4*)(h + (size_t)r1 * D + lane * 4);
            float4 v2 = *(const float4*)(h + (size_t)r2 * D + lane * 4);
            float4 v3 = *(const float4*)(h + (size_t)r3 * D + lane * 4);
            acc[0] += v0.x * n0 + v1.x * n1 + v2.x * n2 + v3.x * n3;
            acc[1] += v0.y * n0 + v1.y * n1 + v2.y * n2 + v3.y * n3;
            acc[2] += v0.z * n0 + v1.z * n1 + v2.z * n2 + v3.z * n3;
            acc[3] += v0.w * n0 + v1.w * n1 + v2.w * n2 + v3.w * n3;
        } else {
            float2 v0 = *(const float2*)(h + (size_t)r0 * D + lane * 2);
            float2 v1 = *(const float2*)(h + (size_t)r1 * D + lane * 2);
            float2 v2 = *(const float2*)(h + (size_t)r2 * D + lane * 2);
            float2 v3 = *(const float2*)(h + (size_t)r3 * D + lane * 2);
            acc[0] += v0.x * n0 + v1.x * n1 + v2.x * n2 + v3.x * n3;
            acc[1] += v0.y * n0 + v1.y * n1 + v2.y * n2 + v3.y * n3;
        }
    }
    for (; s < s1; s++) {
        int r = csr_row[s];
        float nrm = csr_nrm[s];
        const float* hp = h + (size_t)r * D + lane * V;
        if (V == 4) {
            float4 v = *(const float4*)hp;
            acc[0] += v.x * nrm; acc[1] += v.y * nrm;
            acc[2] += v.z * nrm; acc[3] += v.w * nrm;
        } else {
            float2 v = *(const float2*)hp;
            acc[0] += v.x * nrm; acc[1] += v.y * nrm;
        }
    }
    float* op = out + (size_t)node * D + lane * V;
    if (V == 4) *(float4*)op = make_float4(acc[0], acc[1], acc[2], acc[3]);
    else        *(float2*)op = make_float2(acc[0], acc[1]);
}

// ---------------- BN stats ----------------
__global__ void bn_stats_kernel(const float* __restrict__ x, float* sum, float* sq,
                                int Nrows, int d) {
    int c = threadIdx.x;
    float s = 0.f, ss = 0.f;
    for (int r = blockIdx.x; r < Nrows; r += gridDim.x) {
        float v = x[(size_t)r * d + c];
        s += v; ss += v * v;
    }
    atomicAdd(&sum[c], s);
    atomicAdd(&sq[c], ss);
}

__global__ void bn_finalize_kernel(const float* sum, const float* sq,
                                   const float* __restrict__ g, const float* __restrict__ b,
                                   float* scale, float* shift, int d, float invN) {
    int c = threadIdx.x;
    if (c < d) {
        float mu = sum[c] * invN;
        float var = sq[c] * invN - mu * mu;
        float rs = rsqrtf(var + 1e-5f);
        float sc = g[c] * rs;
        scale[c] = sc;
        shift[c] = b[c] - mu * sc;
    }
}

// ---------------- GAT ----------------
__global__ void gat_coef_kernel(const float* __restrict__ hg, const float* __restrict__ a_src,
                                const float* __restrict__ a_dst, float* asrc, float* adst,
                                int Nn, int d) {
    int t = blockIdx.x * blockDim.x + threadIdx.x;
    if (t >= Nn * HEADS) return;
    int n = t >> 2, h = t & 3;
    int C = d >> 2;
    const float* hp = hg + (size_t)n * d + h * C;
    const float* as = a_src + h * C;
    const float* ad = a_dst + h * C;
    float s1 = 0.f, s2 = 0.f;
    for (int c = 0; c < C; c++) { float v = hp[c]; s1 += v * as[c]; s2 += v * ad[c]; }
    asrc[t] = s1;
    adst[t] = s2;
}

// One-pass fused GAT: warp per node, MLP=4 unroll.
template <int D>
__global__ void gat_csr_kernel(const float* __restrict__ hg, const float* __restrict__ asrc,
                               const float* __restrict__ adst, const int* __restrict__ off,
                               const int* __restrict__ csr_row, const float* __restrict__ gb,
                               const float* __restrict__ agg, const float* __restrict__ scl,
                               const float* __restrict__ shf, float* __restrict__ xout, int Nn) {
    int node = (blockIdx.x * blockDim.x + threadIdx.x) >> 5;
    if (node >= Nn) return;
    int lane = threadIdx.x & 31;
    constexpr int V = D / 32;
    int hh = lane >> 3;  // 8 lanes per head
    int s0 = off[node], s1 = off[node + 1];
    float ad = adst[node * 4 + hh];
    float acc[V] = {};
    float sw = 0.f;
    int s = s0;
    for (; s + 4 <= s1; s += 4) {
        int r0 = csr_row[s + 0], r1 = csr_row[s + 1];
        int r2 = csr_row[s + 2], r3 = csr_row[s + 3];
        float e0 = asrc[r0 * 4 + hh], e1 = asrc[r1 * 4 + hh];
        float e2 = asrc[r2 * 4 + hh], e3 = asrc[r3 * 4 + hh];
        float w0 = __expf(lrelu(e0 + ad));
        float w1 = __expf(lrelu(e1 + ad));
        float w2 = __expf(lrelu(e2 + ad));
        float w3 = __expf(lrelu(e3 + ad));
        sw += (w0 + w1) + (w2 + w3);
        if (V == 4) {
            float4 v0 = *(const float4*)(hg + (size_t)r0 * D + lane * 4);
            float4 v1 = *(const float4*)(hg + (size_t)r1 * D + lane * 4);
            float4 v2 = *(const float4*)(hg + (size_t)r2 * D + lane * 4);
            float4 v3 = *(const float4*)(hg + (size_t)r3 * D + lane * 4);
            acc[0] += v0.x * w0 + v1.x * w1 + v2.x * w2 + v3.x * w3;
            acc[1] += v0.y * w0 + v1.y * w1 + v2.y * w2 + v3.y * w3;
            acc[2] += v0.z * w0 + v1.z * w1 + v2.z * w2 + v3.z * w3;
            acc[3] += v0.w * w0 + v1.w * w1 + v2.w * w2 + v3.w * w3;
        } else {
            float2 v0 = *(const float2*)(hg + (size_t)r0 * D + lane * 2);
            float2 v1 = *(const float2*)(hg + (size_t)r1 * D + lane * 2);
            float2 v2 = *(const float2*)(hg + (size_t)r2 * D + lane * 2);
            float2 v3 = *(const float2*)(hg + (size_t)r3 * D + lane * 2);
            acc[0] += v0.x * w0 + v1.x * w1 + v2.x * w2 + v3.x * w3;
            acc[1] += v0.y * w0 + v1.y * w1 + v2.y * w2 + v3.y * w3;
        }
    }
    for (; s < s1; s++) {
        int r = csr_row[s];
        float w = __expf(lrelu(asrc[r * 4 + hh] + ad));
        sw += w;
        const float* hp = hg + (size_t)r * D + lane * V;
        if (V == 4) {
            float4 v = *(const float4*)hp;
            acc[0] += v.x * w; acc[1] += v.y * w;
            acc[2] += v.z * w; acc[3] += v.w * w;
        } else {
            float2 v = *(const float2*)hp;
            acc[0] += v.x * w; acc[1] += v.y * w;
        }
    }
    float inv = 1.f / sw;
    const float* ap = agg + (size_t)node * D + lane * V;
    float* op = xout + (size_t)node * D + lane * V;
#pragma unroll
    for (int k = 0; k < V; k++) {
        int c = lane * V + k;
        float y = ap[k] * scl[c] + shf[c];   // BN'd residual recomputed inline
        float v = acc[k] * inv + gb[c] + y;
        op[k] = lrelu(v);
    }
}

// ---------------- pooling (BN of last layer fused) ----------------
__global__ void pool_accum_bn_kernel(const float* __restrict__ x, const int* __restrict__ batch,
                                     const float* __restrict__ scl, const float* __restrict__ shf,
                                     float* sums, int Nn, int d) {
    int t = blockIdx.x * blockDim.x + threadIdx.x;
    if (t >= Nn * d) return;
    int n = t / d, c = t % d;
    atomicAdd(&sums[batch[n] * d + c], x[t] * scl[c] + shf[c]);
}

__global__ void pool_cnt_kernel(const int* __restrict__ batch, float* cnt, int Nn) {
    int n = blockIdx.x * blockDim.x + threadIdx.x;
    if (n < Nn) atomicAdd(&cnt[batch[n]], 1.0f);
}

__global__ void pool_final_kernel(const float* __restrict__ sums, const float* __restrict__ cnt,
                                  float* __restrict__ out, int G, int d) {
    int t = blockIdx.x * blockDim.x + threadIdx.x;
    if (t >= G * d) return;
    int g = t / d;
    out[t] = sums[t] / fmaxf(cnt[g], 1.0f);
}

// ---------------- host orchestration ----------------
extern "C" void kernel_launch(void* const* d_in, const int* in_sizes, int n_in,
                              void* d_out, int out_size) {
    const float* x_in  = (const float*)d_in[0];
    const int*   ei    = (const int*)d_in[1];
    const int*   batch = (const int*)d_in[2];
    const float* gcn_w[4], *bn_g[4], *bn_b[4];
    for (int i = 0; i < 4; i++) {
        gcn_w[i] = (const float*)d_in[3 + i * 4 + 0];
        bn_g[i]  = (const float*)d_in[3 + i * 4 + 2];
        bn_b[i]  = (const float*)d_in[3 + i * 4 + 3];
    }
    const float* gat_w[2], *gat_as[2], *gat_ad[2], *gat_b[2];
    for (int j = 0; j < 2; j++) {
        gat_w[j]  = (const float*)d_in[19 + j * 4 + 0];
        gat_as[j] = (const float*)d_in[19 + j * 4 + 1];
        gat_ad[j] = (const float*)d_in[19 + j * 4 + 2];
        gat_b[j]  = (const float*)d_in[19 + j * 4 + 3];
    }
    const int Nn = in_sizes[0] / 16;
    const int E  = in_sizes[1] / 2;
    const int* row = ei;
    const int* col = ei + E;

    float *b0, *b1, *b2, *dis, *asrc, *adst;
    float *bnsum, *bnsq, *scl, *shf, *pool, *cnt;
    int *hist, *off, *cur, *csr_row, *blksum;
    float *csr_nrm;
    cudaGetSymbolAddress((void**)&b0, g_b0);
    cudaGetSymbolAddress((void**)&b1, g_b1);
    cudaGetSymbolAddress((void**)&b2, g_b2);
    cudaGetSymbolAddress((void**)&dis, g_dis);
    cudaGetSymbolAddress((void**)&asrc, g_asrc);
    cudaGetSymbolAddress((void**)&adst, g_adst);
    cudaGetSymbolAddress((void**)&bnsum, g_bnsum);
    cudaGetSymbolAddress((void**)&bnsq, g_bnsq);
    cudaGetSymbolAddress((void**)&scl, g_scale);
    cudaGetSymbolAddress((void**)&shf, g_shift);
    cudaGetSymbolAddress((void**)&pool, g_pool);
    cudaGetSymbolAddress((void**)&cnt, g_cnt);
    cudaGetSymbolAddress((void**)&hist, g_hist);
    cudaGetSymbolAddress((void**)&off, g_off);
    cudaGetSymbolAddress((void**)&cur, g_cur);
    cudaGetSymbolAddress((void**)&csr_row, g_csr_row);
    cudaGetSymbolAddress((void**)&csr_nrm, g_csr_nrm);
    cudaGetSymbolAddress((void**)&blksum, g_blksum);

    // ---- CSR build (by target node), self-loop at segment head ----
    const int nb = cdiv(Nn, SCAN_BLK);
    fill_int_kernel<<<cdiv(Nn, 256), 256>>>(hist, 1, Nn);
    hist_kernel<<<cdiv(E, 256), 256>>>(col, hist, E);
    scan1_kernel<<<nb, SCAN_BLK>>>(hist, blksum, Nn);
    scan2_kernel<<<1, 256>>>(blksum, nb);
    scan3_kernel<<<nb, SCAN_BLK>>>(hist, blksum, off, cur, csr_row, csr_nrm, dis, Nn);
    scatter_kernel<<<cdiv(E, 256), 256>>>(row, col, dis, cur, csr_row, csr_nrm, E);

    const int nodeWarpGrid = cdiv(Nn * 32, 256);

    auto stats = [&](const float* agg, int i, int dout) {
        cudaMemsetAsync(bnsum, 0, dout * sizeof(float));
        cudaMemsetAsync(bnsq, 0, dout * sizeof(float));
        bn_stats_kernel<<<512, dout>>>(agg, bnsum, bnsq, Nn, dout);
        bn_finalize_kernel<<<1, dout>>>(bnsum, bnsq, bn_g[i], bn_b[i], scl, shf, dout,
                                        1.0f / (float)Nn);
    };

    // ---- layer 0: GCN(16->64) + BN + GAT + lrelu ----
    gemm_kernel<256, 64, 0><<<dim3(1, cdiv(Nn, 256)), 256>>>(x_in, gcn_w[0], b0, scl, shf, Nn, 64, 16);
    gcn_agg_csr_kernel<64><<<nodeWarpGrid, 256>>>(b0, off, csr_row, csr_nrm, b1, Nn);
    stats(b1, 0, 64);
    gemm_kernel<256, 64, 1><<<dim3(1, cdiv(Nn, 256)), 256>>>(b1, gat_w[0], b0, scl, shf, Nn, 64, 64);
    gat_coef_kernel<<<cdiv(Nn * HEADS, 256), 256>>>(b0, gat_as[0], gat_ad[0], asrc, adst, Nn, 64);
    gat_csr_kernel<64><<<nodeWarpGrid, 256>>>(b0, asrc, adst, off, csr_row, gat_b[0],
                                              b1, scl, shf, b2, Nn);

    // ---- layer 1: GCN(64->128) + BN + lrelu (relu fused into next gemm) ----
    gemm_kernel<128, 128, 0><<<dim3(1, cdiv(Nn, 128)), 256>>>(b2, gcn_w[1], b0, scl, shf, Nn, 128, 64);
    gcn_agg_csr_kernel<128><<<nodeWarpGrid, 256>>>(b0, off, csr_row, csr_nrm, b1, Nn);
    stats(b1, 1, 128);

    // ---- layer 2: GCN(128->128) [A = lrelu(BN(agg1))] + BN + GAT + lrelu ----
    gemm_kernel<128, 128, 2><<<dim3(1, cdiv(Nn, 128)), 256>>>(b1, gcn_w[2], b0, scl, shf, Nn, 128, 128);
    gcn_agg_csr_kernel<128><<<nodeWarpGrid, 256>>>(b0, off, csr_row, csr_nrm, b2, Nn);
    stats(b2, 2, 128);
    gemm_kernel<128, 128, 1><<<dim3(1, cdiv(Nn, 128)), 256>>>(b2, gat_w[1], b0, scl, shf, Nn, 128, 128);
    gat_coef_kernel<<<cdiv(Nn * HEADS, 256), 256>>>(b0, gat_as[1], gat_ad[1], asrc, adst, Nn, 128);
    gat_csr_kernel<128><<<nodeWarpGrid, 256>>>(b0, asrc, adst, off, csr_row, gat_b[1],
                                               b2, scl, shf, b1, Nn);

    // ---- layer 3: GCN(128->64) + BN (no relu, fused into pooling) ----
    gemm_kernel<256, 64, 0><<<dim3(1, cdiv(Nn, 256)), 256>>>(b1, gcn_w[3], b2, scl, shf, Nn, 64, 128);
    gcn_agg_csr_kernel<64><<<nodeWarpGrid, 256>>>(b2, off, csr_row, csr_nrm, b0, Nn);
    stats(b0, 3, 64);

    // ---- global mean pool (BN fused) ----
    const int dfin = 64;
    const int G = out_size / dfin;
    cudaMemsetAsync(pool, 0, (size_t)G * dfin * sizeof(float));
    cudaMemsetAsync(cnt, 0, (size_t)G * sizeof(float));
    pool_accum_bn_kernel<<<cdiv(Nn * dfin, 256), 256>>>(b0, batch, scl, shf, pool, Nn, dfin);
    pool_cnt_kernel<<<cdiv(Nn, 256), 256>>>(batch, cnt, Nn);
    pool_final_kernel<<<cdiv(G * dfin, 256), 256>>>(pool, cnt, (float*)d_out, G, dfin);
}

// round 8
// speedup vs baseline: 1.2267x; 1.2267x over previous
#include <cuda_runtime.h>
#include <cuda_bf16.h>
#include <cstdint>

#define NMAX 100000
#define EMAX 1600000
#define ETOTMAX (NMAX + EMAX)
#define GMAX 256
#define HEADS 4
#define SCAN_BLK 512

// ---------------- scratch (device globals; no allocation allowed) -------------
__device__ float g_b0[NMAX * 128];
__device__ float g_b1[NMAX * 128];
__device__ float g_b2[NMAX * 128];
__device__ float g_dis[NMAX];
__device__ float g_asrc[NMAX * HEADS];
__device__ float g_adst[NMAX * HEADS];
__device__ float g_bnsum[128];
__device__ float g_bnsq[128];
__device__ float g_scale[128];
__device__ float g_shift[128];
__device__ float g_pool[GMAX * 64];
__device__ float g_cnt[GMAX];
__device__ int   g_hist[NMAX];
__device__ int   g_off[NMAX + 1];
__device__ int   g_cur[NMAX];
__device__ int   g_csr_row[ETOTMAX];
__device__ float g_csr_nrm[ETOTMAX];
__device__ int   g_blksum[256];

// ---------------- helpers ----------------
__device__ __forceinline__ float lrelu(float v) { return v > 0.f ? v : 0.2f * v; }
static inline int cdiv(int a, int b) { return (a + b - 1) / b; }

// ---------------- CSR build ----------------
__global__ void fill_int_kernel(int* p, int v, int n) {
    int t = blockIdx.x * blockDim.x + threadIdx.x;
    if (t < n) p[t] = v;
}

__global__ void hist_kernel(const int* __restrict__ col, int* hist, int E) {
    int e = blockIdx.x * blockDim.x + threadIdx.x;
    if (e < E) atomicAdd(&hist[col[e]], 1);
}

__global__ void scan1_kernel(const int* __restrict__ hist, int* blksum, int Nn) {
    __shared__ int sm[SCAN_BLK];
    int i = blockIdx.x * SCAN_BLK + threadIdx.x;
    sm[threadIdx.x] = (i < Nn) ? hist[i] : 0;
    __syncthreads();
    for (int st = SCAN_BLK / 2; st > 0; st >>= 1) {
        if (threadIdx.x < st) sm[threadIdx.x] += sm[threadIdx.x + st];
        __syncthreads();
    }
    if (threadIdx.x == 0) blksum[blockIdx.x] = sm[0];
}

__global__ void scan2_kernel(int* blksum, int nb) {
    __shared__ int sm[256];
    int v = (threadIdx.x < nb) ? blksum[threadIdx.x] : 0;
    sm[threadIdx.x] = v;
    __syncthreads();
    for (int st = 1; st < 256; st <<= 1) {
        int t = (threadIdx.x >= st) ? sm[threadIdx.x - st] : 0;
        __syncthreads();
        sm[threadIdx.x] += t;
        __syncthreads();
    }
    if (threadIdx.x < nb) blksum[threadIdx.x] = sm[threadIdx.x] - v;  // exclusive
}

__global__ void scan3_kernel(const int* __restrict__ hist, const int* __restrict__ blksum,
                             int* off, int* cur, int* csr_row, float* csr_nrm,
                             float* dis, int Nn) {
    __shared__ int sm[SCAN_BLK];
    int i = blockIdx.x * SCAN_BLK + threadIdx.x;
    int v = (i < Nn) ? hist[i] : 0;
    sm[threadIdx.x] = v;
    __syncthreads();
    for (int st = 1; st < SCAN_BLK; st <<= 1) {
        int t = (threadIdx.x >= st) ? sm[threadIdx.x - st] : 0;
        __syncthreads();
        sm[threadIdx.x] += t;
        __syncthreads();
    }
    if (i < Nn) {
        int excl = sm[threadIdx.x] - v + blksum[blockIdx.x];
        off[i] = excl;
        cur[i] = excl + 1;              // slot excl reserved for self-loop
        dis[i] = rsqrtf((float)v);
        csr_row[excl] = i;
        csr_nrm[excl] = 1.0f / (float)v;
        if (i == Nn - 1) off[Nn] = excl + v;
    }
}

__global__ void scatter_kernel(const int* __restrict__ row, const int* __restrict__ col,
                               const float* __restrict__ dis, int* cur,
                               int* csr_row, float* csr_nrm, int E) {
    int e = blockIdx.x * blockDim.x + threadIdx.x;
    if (e >= E) return;
    int r = row[e], c = col[e];
    int pos = atomicAdd(&cur[c], 1);
    csr_row[pos] = r;
    csr_nrm[pos] = dis[r] * dis[c];
}

// ---------------- GEMM (R3 single-buffer form + fused epilogues) ----------------
// C[M,N] = op(A)[M,K] @ B[K,N].
// MODE: 0 = raw A, 1 = A*scl+shf, 2 = lrelu(A*scl+shf)
// EPI:  0 = none
//       1 = BN stats: ep1 += per-channel sum of C, ep2 += per-channel sumsq
//       2 = GAT coef: ep1[row*4+h] += C[row,:]·avs, ep2[row*4+h] += C[row,:]·avd
template <int BM, int BN, int MODE, int EPI>
__global__ void __launch_bounds__(256) gemm_kernel(
    const float* __restrict__ A, const float* __restrict__ B, float* __restrict__ C,
    const float* __restrict__ scl, const float* __restrict__ shf,
    float* ep1, float* ep2, const float* __restrict__ avs, const float* __restrict__ avd,
    int M, int N, int K) {
    constexpr int TM = BM / 16, TN = BN / 16;
    __shared__ float As[16][BM + 4];
    __shared__ float Bs[16][BN];
    __shared__ float sm_s[BN], sm_q[BN];
    int tid = threadIdx.x;
    int tx = tid & 15, ty = tid >> 4;
    int rowBase = blockIdx.y * BM;
    int colBase = blockIdx.x * BN;
    float acc[TM][TN] = {};
    for (int k0 = 0; k0 < K; k0 += 16) {
        constexpr int ALOADS = BM * 4 / 256;  // float4 loads per thread
#pragma unroll
        for (int i = 0; i < ALOADS; i++) {
            int idx = tid + i * 256;
            int r = idx >> 2, q = idx & 3;
            int gr = rowBase + r;
            float4 v = make_float4(0.f, 0.f, 0.f, 0.f);
            if (gr < M) v = *(const float4*)&A[(size_t)gr * K + k0 + q * 4];
            if (MODE >= 1) {
                float4 s4 = *(const float4*)&scl[k0 + q * 4];
                float4 h4 = *(const float4*)&shf[k0 + q * 4];
                v.x = v.x * s4.x + h4.x; v.y = v.y * s4.y + h4.y;
                v.z = v.z * s4.z + h4.z; v.w = v.w * s4.w + h4.w;
                if (MODE == 2) { v.x = lrelu(v.x); v.y = lrelu(v.y); v.z = lrelu(v.z); v.w = lrelu(v.w); }
            }
            As[q * 4 + 0][r] = v.x; As[q * 4 + 1][r] = v.y;
            As[q * 4 + 2][r] = v.z; As[q * 4 + 3][r] = v.w;
        }
        constexpr int BLOADS = BN * 16 / 4 / 256;
#pragma unroll
        for (int i = 0; i < BLOADS; i++) {
            int idx = tid + i * 256;
            int r = idx / (BN / 4), c = idx % (BN / 4);
            *(float4*)&Bs[r][c * 4] = *(const float4*)&B[(size_t)(k0 + r) * N + colBase + c * 4];
        }
        __syncthreads();
#pragma unroll
        for (int kk = 0; kk < 16; kk++) {
            float a[TM], b[TN];
#pragma unroll
            for (int m = 0; m < TM; m += 4)
                *(float4*)&a[m] = *(const float4*)&As[kk][ty * TM + m];
#pragma unroll
            for (int n = 0; n < TN; n += 4)
                *(float4*)&b[n] = *(const float4*)&Bs[kk][tx * TN + n];
#pragma unroll
            for (int m = 0; m < TM; m++)
#pragma unroll
                for (int n = 0; n < TN; n++) acc[m][n] += a[m] * b[n];
        }
        __syncthreads();
    }
#pragma unroll
    for (int m = 0; m < TM; m++) {
        int gr = rowBase + ty * TM + m;
        if (gr < M) {
#pragma unroll
            for (int n = 0; n < TN; n += 4) {
                float4 v = make_float4(acc[m][n], acc[m][n + 1], acc[m][n + 2], acc[m][n + 3]);
                *(float4*)&C[(size_t)gr * N + colBase + tx * TN + n] = v;
            }
        }
    }
    if (EPI == 1) {
        // per-channel sum / sumsq of this block's C tile (pad rows contribute 0 under MODE 0)
        if (tid < BN) { sm_s[tid] = 0.f; sm_q[tid] = 0.f; }
        __syncthreads();
#pragma unroll
        for (int n = 0; n < TN; n++) {
            float s = 0.f, q = 0.f;
#pragma unroll
            for (int m = 0; m < TM; m++) {
                int gr = rowBase + ty * TM + m;
                if (gr < M) { float v = acc[m][n]; s += v; q += v * v; }
            }
            atomicAdd(&sm_s[tx * TN + n], s);
            atomicAdd(&sm_q[tx * TN + n], q);
        }
        __syncthreads();
        if (tid < BN) {
            atomicAdd(&ep1[tid], sm_s[tid]);
            atomicAdd(&ep2[tid], sm_q[tid]);
        }
    }
    if (EPI == 2) {
        // attention coefficients: all TN cols of a thread lie in one head
        int head = tx >> 2;
#pragma unroll
        for (int m = 0; m < TM; m++) {
            int gr = rowBase + ty * TM + m;
            if (gr < M) {
                float s1 = 0.f, s2 = 0.f;
#pragma unroll
                for (int n = 0; n < TN; n++) {
                    int c = tx * TN + n;
                    s1 += acc[m][n] * avs[c];
                    s2 += acc[m][n] * avd[c];
                }
                atomicAdd(&ep1[gr * 4 + head], s1);
                atomicAdd(&ep2[gr * 4 + head], s2);
            }
        }
    }
}

// ---------------- GCN aggregation: warp per node, CSR gather ----------------
template <int D>
__global__ void gcn_agg_csr_kernel(const float* __restrict__ h, const int* __restrict__ off,
                                   const int* __restrict__ csr_row,
                                   const float* __restrict__ csr_nrm,
                                   float* __restrict__ out, int Nn) {
    int node = (blockIdx.x * blockDim.x + threadIdx.x) >> 5;
    if (node >= Nn) return;
    int lane = threadIdx.x & 31;
    constexpr int V = D / 32;
    int s0 = off[node], s1 = off[node + 1];
    float acc[V] = {};
    for (int s = s0; s < s1; s++) {
        int r = csr_row[s];
        float nrm = csr_nrm[s];
        const float* hp = h + (size_t)r * D + lane * V;
        if (V == 4) {
            float4 v = *(const float4*)hp;
            acc[0] += v.x * nrm; acc[1] += v.y * nrm;
            acc[2] += v.z * nrm; acc[3] += v.w * nrm;
        } else {
            float2 v = *(const float2*)hp;
            acc[0] += v.x * nrm; acc[1] += v.y * nrm;
        }
    }
    float* op = out + (size_t)node * D + lane * V;
    if (V == 4) *(float4*)op = make_float4(acc[0], acc[1], acc[2], acc[3]);
    else        *(float2*)op = make_float2(acc[0], acc[1]);
}

// D=16 variant (aggregation of raw input): lanes 0..15 hold one channel each
__global__ void gcn_agg_csr16_kernel(const float* __restrict__ x, const int* __restrict__ off,
                                     const int* __restrict__ csr_row,
                                     const float* __restrict__ csr_nrm,
                                     float* __restrict__ out, int Nn) {
    int node = (blockIdx.x * blockDim.x + threadIdx.x) >> 5;
    if (node >= Nn) return;
    int lane = threadIdx.x & 31;
    int s0 = off[node], s1 = off[node + 1];
    float acc = 0.f;
    for (int s = s0; s < s1; s++) {
        int r = csr_row[s];
        float nrm = csr_nrm[s];
        if (lane < 16) acc += x[(size_t)r * 16 + lane] * nrm;
    }
    if (lane < 16) out[(size_t)node * 16 + lane] = acc;
}

// ---------------- BN stats (still used for post-aggregation layers 2,3) -------
__global__ void bn_stats_kernel(const float* __restrict__ x, float* sum, float* sq,
                                int Nrows, int d) {
    int c = threadIdx.x;
    float s = 0.f, ss = 0.f;
    for (int r = blockIdx.x; r < Nrows; r += gridDim.x) {
        float v = x[(size_t)r * d + c];
        s += v; ss += v * v;
    }
    atomicAdd(&sum[c], s);
    atomicAdd(&sq[c], ss);
}

__global__ void bn_finalize_kernel(const float* sum, const float* sq,
                                   const float* __restrict__ g, const float* __restrict__ b,
                                   float* scale, float* shift, int d, float invN) {
    int c = threadIdx.x;
    if (c < d) {
        float mu = sum[c] * invN;
        float var = sq[c] * invN - mu * mu;
        float rs = rsqrtf(var + 1e-5f);
        float sc = g[c] * rs;
        scale[c] = sc;
        shift[c] = b[c] - mu * sc;
    }
}

// ---------------- GAT: one-pass fused, warp per node ----------------
template <int D>
__global__ void gat_csr_kernel(const float* __restrict__ hg, const float* __restrict__ asrc,
                               const float* __restrict__ adst, const int* __restrict__ off,
                               const int* __restrict__ csr_row, const float* __restrict__ gb,
                               const float* __restrict__ agg, const float* __restrict__ scl,
                               const float* __restrict__ shf, float* __restrict__ xout, int Nn) {
    int node = (blockIdx.x * blockDim.x + threadIdx.x) >> 5;
    if (node >= Nn) return;
    int lane = threadIdx.x & 31;
    constexpr int V = D / 32;
    int hh = lane >> 3;  // 8 lanes per head
    int s0 = off[node], s1 = off[node + 1];
    float ad = adst[node * 4 + hh];
    float acc[V] = {};
    float sw = 0.f;
    for (int s = s0; s < s1; s++) {
        int r = csr_row[s];
        float e = lrelu(asrc[r * 4 + hh] + ad);
        float w = __expf(e);
        sw += w;
        const float* hp = hg + (size_t)r * D + lane * V;
        if (V == 4) {
            float4 v = *(const float4*)hp;
            acc[0] += v.x * w; acc[1] += v.y * w;
            acc[2] += v.z * w; acc[3] += v.w * w;
        } else {
            float2 v = *(const float2*)hp;
            acc[0] += v.x * w; acc[1] += v.y * w;
        }
    }
    float inv = 1.f / sw;
    const float* ap = agg + (size_t)node * D + lane * V;
    float* op = xout + (size_t)node * D + lane * V;
#pragma unroll
    for (int k = 0; k < V; k++) {
        int c = lane * V + k;
        float y = ap[k] * scl[c] + shf[c];   // BN'd residual recomputed inline
        float v = acc[k] * inv + gb[c] + y;
        op[k] = lrelu(v);
    }
}

// ---------------- pooling (BN of last layer fused) ----------------
__global__ void pool_accum_bn_kernel(const float* __restrict__ x, const int* __restrict__ batch,
                                     const float* __restrict__ scl, const float* __restrict__ shf,
                                     float* sums, int Nn, int d) {
    int t = blockIdx.x * blockDim.x + threadIdx.x;
    if (t >= Nn * d) return;
    int n = t / d, c = t % d;
    atomicAdd(&sums[batch[n] * d + c], x[t] * scl[c] + shf[c]);
}

__global__ void pool_cnt_kernel(const int* __restrict__ batch, float* cnt, int Nn) {
    int n = blockIdx.x * blockDim.x + threadIdx.x;
    if (n < Nn) atomicAdd(&cnt[batch[n]], 1.0f);
}

__global__ void pool_final_kernel(const float* __restrict__ sums, const float* __restrict__ cnt,
                                  float* __restrict__ out, int G, int d) {
    int t = blockIdx.x * blockDim.x + threadIdx.x;
    if (t >= G * d) return;
    int g = t / d;
    out[t] = sums[t] / fmaxf(cnt[g], 1.0f);
}

// ---------------- host orchestration ----------------
extern "C" void kernel_launch(void* const* d_in, const int* in_sizes, int n_in,
                              void* d_out, int out_size) {
    const float* x_in  = (const float*)d_in[0];
    const int*   ei    = (const int*)d_in[1];
    const int*   batch = (const int*)d_in[2];
    const float* gcn_w[4], *bn_g[4], *bn_b[4];
    for (int i = 0; i < 4; i++) {
        gcn_w[i] = (const float*)d_in[3 + i * 4 + 0];
        bn_g[i]  = (const float*)d_in[3 + i * 4 + 2];
        bn_b[i]  = (const float*)d_in[3 + i * 4 + 3];
    }
    const float* gat_w[2], *gat_as[2], *gat_ad[2], *gat_b[2];
    for (int j = 0; j < 2; j++) {
        gat_w[j]  = (const float*)d_in[19 + j * 4 + 0];
        gat_as[j] = (const float*)d_in[19 + j * 4 + 1];
        gat_ad[j] = (const float*)d_in[19 + j * 4 + 2];
        gat_b[j]  = (const float*)d_in[19 + j * 4 + 3];
    }
    const int Nn = in_sizes[0] / 16;
    const int E  = in_sizes[1] / 2;
    const int* row = ei;
    const int* col = ei + E;

    float *b0, *b1, *b2, *dis, *asrc, *adst;
    float *bnsum, *bnsq, *scl, *shf, *pool, *cnt;
    int *hist, *off, *cur, *csr_row, *blksum;
    float *csr_nrm;
    cudaGetSymbolAddress((void**)&b0, g_b0);
    cudaGetSymbolAddress((void**)&b1, g_b1);
    cudaGetSymbolAddress((void**)&b2, g_b2);
    cudaGetSymbolAddress((void**)&dis, g_dis);
    cudaGetSymbolAddress((void**)&asrc, g_asrc);
    cudaGetSymbolAddress((void**)&adst, g_adst);
    cudaGetSymbolAddress((void**)&bnsum, g_bnsum);
    cudaGetSymbolAddress((void**)&bnsq, g_bnsq);
    cudaGetSymbolAddress((void**)&scl, g_scale);
    cudaGetSymbolAddress((void**)&shf, g_shift);
    cudaGetSymbolAddress((void**)&pool, g_pool);
    cudaGetSymbolAddress((void**)&cnt, g_cnt);
    cudaGetSymbolAddress((void**)&hist, g_hist);
    cudaGetSymbolAddress((void**)&off, g_off);
    cudaGetSymbolAddress((void**)&cur, g_cur);
    cudaGetSymbolAddress((void**)&csr_row, g_csr_row);
    cudaGetSymbolAddress((void**)&csr_nrm, g_csr_nrm);
    cudaGetSymbolAddress((void**)&blksum, g_blksum);

    // ---- CSR build (by target node), self-loop at segment head ----
    const int nb = cdiv(Nn, SCAN_BLK);
    fill_int_kernel<<<cdiv(Nn, 256), 256>>>(hist, 1, Nn);
    hist_kernel<<<cdiv(E, 256), 256>>>(col, hist, E);
    scan1_kernel<<<nb, SCAN_BLK>>>(hist, blksum, Nn);
    scan2_kernel<<<1, 256>>>(blksum, nb);
    scan3_kernel<<<nb, SCAN_BLK>>>(hist, blksum, off, cur, csr_row, csr_nrm, dis, Nn);
    scatter_kernel<<<cdiv(E, 256), 256>>>(row, col, dis, cur, csr_row, csr_nrm, E);

    const int nodeWarpGrid = cdiv(Nn * 32, 256);
    const float invN = 1.0f / (float)Nn;

    auto clear_stats = [&]() {
        cudaMemsetAsync(bnsum, 0, 128 * sizeof(float));
        cudaMemsetAsync(bnsq, 0, 128 * sizeof(float));
    };
    auto clear_coef = [&]() {
        cudaMemsetAsync(asrc, 0, (size_t)Nn * HEADS * sizeof(float));
        cudaMemsetAsync(adst, 0, (size_t)Nn * HEADS * sizeof(float));
    };

    // ---- layer 0: agg in 16-dim (commuted), GEMM(16->64)+stats, GAT ----
    gcn_agg_csr16_kernel<<<nodeWarpGrid, 256>>>(x_in, off, csr_row, csr_nrm, b0, Nn);
    clear_stats();
    gemm_kernel<256, 64, 0, 1><<<dim3(1, cdiv(Nn, 256)), 256>>>(
        b0, gcn_w[0], b1, scl, shf, bnsum, bnsq, nullptr, nullptr, Nn, 64, 16);
    bn_finalize_kernel<<<1, 64>>>(bnsum, bnsq, bn_g[0], bn_b[0], scl, shf, 64, invN);
    clear_coef();
    gemm_kernel<256, 64, 1, 2><<<dim3(1, cdiv(Nn, 256)), 256>>>(
        b1, gat_w[0], b0, scl, shf, asrc, adst, gat_as[0], gat_ad[0], Nn, 64, 64);
    gat_csr_kernel<64><<<nodeWarpGrid, 256>>>(b0, asrc, adst, off, csr_row, gat_b[0],
                                              b1, scl, shf, b2, Nn);

    // ---- layer 1: agg in 64-dim (commuted), GEMM(64->128)+stats ----
    gcn_agg_csr_kernel<64><<<nodeWarpGrid, 256>>>(b2, off, csr_row, csr_nrm, b0, Nn);
    clear_stats();
    gemm_kernel<128, 128, 0, 1><<<dim3(1, cdiv(Nn, 128)), 256>>>(
        b0, gcn_w[1], b1, scl, shf, bnsum, bnsq, nullptr, nullptr, Nn, 128, 64);
    bn_finalize_kernel<<<1, 128>>>(bnsum, bnsq, bn_g[1], bn_b[1], scl, shf, 128, invN);

    // ---- layer 2: GEMM(lrelu(BN(h1)) -> 128), agg128, stats, GAT ----
    gemm_kernel<128, 128, 2, 0><<<dim3(1, cdiv(Nn, 128)), 256>>>(
        b1, gcn_w[2], b0, scl, shf, nullptr, nullptr, nullptr, nullptr, Nn, 128, 128);
    gcn_agg_csr_kernel<128><<<nodeWarpGrid, 256>>>(b0, off, csr_row, csr_nrm, b2, Nn);
    clear_stats();
    bn_stats_kernel<<<512, 128>>>(b2, bnsum, bnsq, Nn, 128);
    bn_finalize_kernel<<<1, 128>>>(bnsum, bnsq, bn_g[2], bn_b[2], scl, shf, 128, invN);
    clear_coef();
    gemm_kernel<128, 128, 1, 2><<<dim3(1, cdiv(Nn, 128)), 256>>>(
        b2, gat_w[1], b0, scl, shf, asrc, adst, gat_as[1], gat_ad[1], Nn, 128, 128);
    gat_csr_kernel<128><<<nodeWarpGrid, 256>>>(b0, asrc, adst, off, csr_row, gat_b[1],
                                               b2, scl, shf, b1, Nn);

    // ---- layer 3: GEMM(128->64), agg64, stats (BN fused into pooling) ----
    gemm_kernel<256, 64, 0, 0><<<dim3(1, cdiv(Nn, 256)), 256>>>(
        b1, gcn_w[3], b0, scl, shf, nullptr, nullptr, nullptr, nullptr, Nn, 64, 128);
    gcn_agg_csr_kernel<64><<<nodeWarpGrid, 256>>>(b0, off, csr_row, csr_nrm, b2, Nn);
    clear_stats();
    bn_stats_kernel<<<512, 64>>>(b2, bnsum, bnsq, Nn, 64);
    bn_finalize_kernel<<<1, 64>>>(bnsum, bnsq, bn_g[3], bn_b[3], scl, shf, 64, invN);

    // ---- global mean pool (BN fused) ----
    const int dfin = 64;
    const int G = out_size / dfin;
    cudaMemsetAsync(pool, 0, (size_t)G * dfin * sizeof(float));
    cudaMemsetAsync(cnt, 0, (size_t)G * sizeof(float));
    pool_accum_bn_kernel<<<cdiv(Nn * dfin, 256), 256>>>(b2, batch, scl, shf, pool, Nn, dfin);
    pool_cnt_kernel<<<cdiv(Nn, 256), 256>>>(batch, cnt, Nn);
    pool_final_kernel<<<cdiv(G * dfin, 256), 256>>>(pool, cnt, (float*)d_out, G, dfin);
}

// round 10
// speedup vs baseline: 1.3213x; 1.0771x over previous
#include <cuda_runtime.h>
#include <cuda_bf16.h>
#include <cuda_fp16.h>
#include <cstdint>

#define NMAX 100000
#define EMAX 1600000
#define ETOTMAX (NMAX + EMAX)
#define GMAX 256
#define HEADS 4
#define SCAN_BLK 512

// ---------------- scratch (device globals; no allocation allowed) -------------
__device__ float g_b0[NMAX * 128];
__device__ float g_b1[NMAX * 128];
__device__ float g_b2[NMAX * 128];
__device__ float g_dis[NMAX];
__device__ float g_asrc[NMAX * HEADS];
__device__ float g_adst[NMAX * HEADS];
__device__ float g_bnsum[128];
__device__ float g_bnsq[128];
__device__ float g_scale[128];
__device__ float g_shift[128];
__device__ float g_pool[GMAX * 64];
__device__ float g_cnt[GMAX];
__device__ int   g_hist[NMAX];
__device__ int   g_off[NMAX + 1];
__device__ int   g_cur[NMAX];
__device__ int   g_csr_row[ETOTMAX];
__device__ float g_csr_nrm[ETOTMAX];
__device__ int   g_blksum[256];

// ---------------- helpers ----------------
__device__ __forceinline__ float lrelu(float v) { return v > 0.f ? v : 0.2f * v; }
static inline int cdiv(int a, int b) { return (a + b - 1) / b; }

// ---------------- CSR build ----------------
__global__ void fill_int_kernel(int* p, int v, int n) {
    int t = blockIdx.x * blockDim.x + threadIdx.x;
    if (t < n) p[t] = v;
}

__global__ void hist_kernel(const int* __restrict__ col, int* hist, int E) {
    int e = blockIdx.x * blockDim.x + threadIdx.x;
    if (e < E) atomicAdd(&hist[col[e]], 1);
}

__global__ void scan1_kernel(const int* __restrict__ hist, int* blksum, int Nn) {
    __shared__ int sm[SCAN_BLK];
    int i = blockIdx.x * SCAN_BLK + threadIdx.x;
    sm[threadIdx.x] = (i < Nn) ? hist[i] : 0;
    __syncthreads();
    for (int st = SCAN_BLK / 2; st > 0; st >>= 1) {
        if (threadIdx.x < st) sm[threadIdx.x] += sm[threadIdx.x + st];
        __syncthreads();
    }
    if (threadIdx.x == 0) blksum[blockIdx.x] = sm[0];
}

__global__ void scan2_kernel(int* blksum, int nb) {
    __shared__ int sm[256];
    int v = (threadIdx.x < nb) ? blksum[threadIdx.x] : 0;
    sm[threadIdx.x] = v;
    __syncthreads();
    for (int st = 1; st < 256; st <<= 1) {
        int t = (threadIdx.x >= st) ? sm[threadIdx.x - st] : 0;
        __syncthreads();
        sm[threadIdx.x] += t;
        __syncthreads();
    }
    if (threadIdx.x < nb) blksum[threadIdx.x] = sm[threadIdx.x] - v;  // exclusive
}

__global__ void scan3_kernel(const int* __restrict__ hist, const int* __restrict__ blksum,
                             int* off, int* cur, int* csr_row, float* csr_nrm,
                             float* dis, int Nn) {
    __shared__ int sm[SCAN_BLK];
    int i = blockIdx.x * SCAN_BLK + threadIdx.x;
    int v = (i < Nn) ? hist[i] : 0;
    sm[threadIdx.x] = v;
    __syncthreads();
    for (int st = 1; st < SCAN_BLK; st <<= 1) {
        int t = (threadIdx.x >= st) ? sm[threadIdx.x - st] : 0;
        __syncthreads();
        sm[threadIdx.x] += t;
        __syncthreads();
    }
    if (i < Nn) {
        int excl = sm[threadIdx.x] - v + blksum[blockIdx.x];
        off[i] = excl;
        cur[i] = excl + 1;              // slot excl reserved for self-loop
        dis[i] = rsqrtf((float)v);
        csr_row[excl] = i;
        csr_nrm[excl] = 1.0f / (float)v;
        if (i == Nn - 1) off[Nn] = excl + v;
    }
}

__global__ void scatter_kernel(const int* __restrict__ row, const int* __restrict__ col,
                               const float* __restrict__ dis, int* cur,
                               int* csr_row, float* csr_nrm, int E) {
    int e = blockIdx.x * blockDim.x + threadIdx.x;
    if (e >= E) return;
    int r = row[e], c = col[e];
    int pos = atomicAdd(&cur[c], 1);
    csr_row[pos] = r;
    csr_nrm[pos] = dis[r] * dis[c];
}

// ---------------- GEMM ----------------
// C[M,N] = op(A)[M,K] @ B[K,N].
// MODE: 0 = raw A, 1 = A*scl+shf, 2 = lrelu(A*scl+shf)
// EPI:  0 none | 1 BN stats (ep1 += colsum, ep2 += colsumsq)
//       2 GAT coef (ep1[r*4+h] += C.avs, ep2[r*4+h] += C.avd)
// OUTH: 0 = fp32 C, 1 = fp16 C
template <int BM, int BN, int MODE, int EPI, int OUTH>
__global__ void __launch_bounds__(256) gemm_kernel(
    const float* __restrict__ A, const float* __restrict__ B, void* __restrict__ Cv,
    const float* __restrict__ scl, const float* __restrict__ shf,
    float* ep1, float* ep2, const float* __restrict__ avs, const float* __restrict__ avd,
    int M, int N, int K) {
    constexpr int TM = BM / 16, TN = BN / 16;
    __shared__ float As[16][BM + 4];
    __shared__ float Bs[16][BN];
    __shared__ float sm_s[BN], sm_q[BN];
    int tid = threadIdx.x;
    int tx = tid & 15, ty = tid >> 4;
    int rowBase = blockIdx.y * BM;
    int colBase = blockIdx.x * BN;
    float acc[TM][TN] = {};
    for (int k0 = 0; k0 < K; k0 += 16) {
        constexpr int ALOADS = BM * 4 / 256;
#pragma unroll
        for (int i = 0; i < ALOADS; i++) {
            int idx = tid + i * 256;
            int r = idx >> 2, q = idx & 3;
            int gr = rowBase + r;
            float4 v = make_float4(0.f, 0.f, 0.f, 0.f);
            if (gr < M) v = *(const float4*)&A[(size_t)gr * K + k0 + q * 4];
            if (MODE >= 1) {
                float4 s4 = *(const float4*)&scl[k0 + q * 4];
                float4 h4 = *(const float4*)&shf[k0 + q * 4];
                v.x = v.x * s4.x + h4.x; v.y = v.y * s4.y + h4.y;
                v.z = v.z * s4.z + h4.z; v.w = v.w * s4.w + h4.w;
                if (MODE == 2) { v.x = lrelu(v.x); v.y = lrelu(v.y); v.z = lrelu(v.z); v.w = lrelu(v.w); }
            }
            As[q * 4 + 0][r] = v.x; As[q * 4 + 1][r] = v.y;
            As[q * 4 + 2][r] = v.z; As[q * 4 + 3][r] = v.w;
        }
        constexpr int BLOADS = BN * 16 / 4 / 256;
#pragma unroll
        for (int i = 0; i < BLOADS; i++) {
            int idx = tid + i * 256;
            int r = idx / (BN / 4), c = idx % (BN / 4);
            *(float4*)&Bs[r][c * 4] = *(const float4*)&B[(size_t)(k0 + r) * N + colBase + c * 4];
        }
        __syncthreads();
#pragma unroll
        for (int kk = 0; kk < 16; kk++) {
            float a[TM], b[TN];
#pragma unroll
            for (int m = 0; m < TM; m += 4)
                *(float4*)&a[m] = *(const float4*)&As[kk][ty * TM + m];
#pragma unroll
            for (int n = 0; n < TN; n += 4)
                *(float4*)&b[n] = *(const float4*)&Bs[kk][tx * TN + n];
#pragma unroll
            for (int m = 0; m < TM; m++)
#pragma unroll
                for (int n = 0; n < TN; n++) acc[m][n] += a[m] * b[n];
        }
        __syncthreads();
    }
#pragma unroll
    for (int m = 0; m < TM; m++) {
        int gr = rowBase + ty * TM + m;
        if (gr < M) {
            if (!OUTH) {
                float* C = (float*)Cv;
#pragma unroll
                for (int n = 0; n < TN; n += 4) {
                    float4 v = make_float4(acc[m][n], acc[m][n + 1], acc[m][n + 2], acc[m][n + 3]);
                    *(float4*)&C[(size_t)gr * N + colBase + tx * TN + n] = v;
                }
            } else {
                __half* C = (__half*)Cv;
#pragma unroll
                for (int n = 0; n < TN; n += 2) {
                    __half2 h = __floats2half2_rn(acc[m][n], acc[m][n + 1]);
                    *(__half2*)&C[(size_t)gr * N + colBase + tx * TN + n] = h;
                }
            }
        }
    }
    if (EPI == 1) {
        if (tid < BN) { sm_s[tid] = 0.f; sm_q[tid] = 0.f; }
        __syncthreads();
#pragma unroll
        for (int n = 0; n < TN; n++) {
            float s = 0.f, q = 0.f;
#pragma unroll
            for (int m = 0; m < TM; m++) {
                int gr = rowBase + ty * TM + m;
                if (gr < M) { float v = acc[m][n]; s += v; q += v * v; }
            }
            atomicAdd(&sm_s[tx * TN + n], s);
            atomicAdd(&sm_q[tx * TN + n], q);
        }
        __syncthreads();
        if (tid < BN) {
            atomicAdd(&ep1[tid], sm_s[tid]);
            atomicAdd(&ep2[tid], sm_q[tid]);
        }
    }
    if (EPI == 2) {
        int head = tx >> 2;
#pragma unroll
        for (int m = 0; m < TM; m++) {
            int gr = rowBase + ty * TM + m;
            if (gr < M) {
                float s1 = 0.f, s2 = 0.f;
#pragma unroll
                for (int n = 0; n < TN; n++) {
                    int c = tx * TN + n;
                    s1 += acc[m][n] * avs[c];
                    s2 += acc[m][n] * avd[c];
                }
                atomicAdd(&ep1[gr * 4 + head], s1);
                atomicAdd(&ep2[gr * 4 + head], s2);
            }
        }
    }
}

// ------------- GCN aggregation: warp per node, fp16 gather, optional stats -------------
template <int D, int STATS>
__global__ void gcn_agg_h_kernel(const __half* __restrict__ h, const int* __restrict__ off,
                                 const int* __restrict__ csr_row,
                                 const float* __restrict__ csr_nrm,
                                 float* __restrict__ out, float* bnsum, float* bnsq, int Nn) {
    __shared__ float s_s[STATS ? D : 1];
    __shared__ float s_q[STATS ? D : 1];
    int tid = threadIdx.x;
    if (STATS) {
        if (tid < D) { s_s[tid] = 0.f; s_q[tid] = 0.f; }
        __syncthreads();
    }
    int node = (blockIdx.x * blockDim.x + tid) >> 5;
    int lane = tid & 31;
    constexpr int V = D / 32;
    float acc[V] = {};
    bool active = node < Nn;
    if (active) {
        int s0 = off[node], s1 = off[node + 1];
        for (int s = s0; s < s1; s++) {
            int r = csr_row[s];
            float nrm = csr_nrm[s];
            const __half* hp = h + (size_t)r * D + lane * V;
            if (V == 4) {
                uint2 u = *(const uint2*)hp;
                float2 f0 = __half22float2(*(const __half2*)&u.x);
                float2 f1 = __half22float2(*(const __half2*)&u.y);
                acc[0] += f0.x * nrm; acc[1] += f0.y * nrm;
                acc[2] += f1.x * nrm; acc[3] += f1.y * nrm;
            } else {
                float2 f0 = __half22float2(*(const __half2*)hp);
                acc[0] += f0.x * nrm; acc[1] += f0.y * nrm;
            }
        }
        float* op = out + (size_t)node * D + lane * V;
        if (V == 4) *(float4*)op = make_float4(acc[0], acc[1], acc[2], acc[3]);
        else        *(float2*)op = make_float2(acc[0], acc[1]);
    }
    if (STATS) {
        if (active) {
#pragma unroll
            for (int k = 0; k < V; k++) {
                atomicAdd(&s_s[lane * V + k], acc[k]);
                atomicAdd(&s_q[lane * V + k], acc[k] * acc[k]);
            }
        }
        __syncthreads();
        if (tid < D) {
            atomicAdd(&bnsum[tid], s_s[tid]);
            atomicAdd(&bnsq[tid], s_q[tid]);
        }
    }
}

// D=16 variant on raw fp32 input
__global__ void gcn_agg_csr16_kernel(const float* __restrict__ x, const int* __restrict__ off,
                                     const int* __restrict__ csr_row,
                                     const float* __restrict__ csr_nrm,
                                     float* __restrict__ out, int Nn) {
    int node = (blockIdx.x * blockDim.x + threadIdx.x) >> 5;
    if (node >= Nn) return;
    int lane = threadIdx.x & 31;
    int s0 = off[node], s1 = off[node + 1];
    float acc = 0.f;
    for (int s = s0; s < s1; s++) {
        int r = csr_row[s];
        float nrm = csr_nrm[s];
        if (lane < 16) acc += x[(size_t)r * 16 + lane] * nrm;
    }
    if (lane < 16) out[(size_t)node * 16 + lane] = acc;
}

// ---------------- BN finalize ----------------
__global__ void bn_finalize_kernel(const float* sum, const float* sq,
                                   const float* __restrict__ g, const float* __restrict__ b,
                                   float* scale, float* shift, int d, float invN) {
    int c = threadIdx.x;
    if (c < d) {
        float mu = sum[c] * invN;
        float var = sq[c] * invN - mu * mu;
        float rs = rsqrtf(var + 1e-5f);
        float sc = g[c] * rs;
        scale[c] = sc;
        shift[c] = b[c] - mu * sc;
    }
}

// ---------------- GAT: one-pass fused, warp per node, fp16 gather ----------------
// OUTH: 1 = fp16 output (next consumer is a gather), 0 = fp32 output (next is GEMM)
template <int D, int OUTH>
__global__ void gat_csr_kernel(const __half* __restrict__ hg, const float* __restrict__ asrc,
                               const float* __restrict__ adst, const int* __restrict__ off,
                               const int* __restrict__ csr_row, const float* __restrict__ gb,
                               const float* __restrict__ agg, const float* __restrict__ scl,
                               const float* __restrict__ shf, void* __restrict__ xoutv, int Nn) {
    int node = (blockIdx.x * blockDim.x + threadIdx.x) >> 5;
    if (node >= Nn) return;
    int lane = threadIdx.x & 31;
    constexpr int V = D / 32;
    int hh = lane >> 3;  // 8 lanes per head
    int s0 = off[node], s1 = off[node + 1];
    float ad = adst[node * 4 + hh];
    float acc[V] = {};
    float sw = 0.f;
    for (int s = s0; s < s1; s++) {
        int r = csr_row[s];
        float e = lrelu(asrc[r * 4 + hh] + ad);
        float w = __expf(e);
        sw += w;
        const __half* hp = hg + (size_t)r * D + lane * V;
        if (V == 4) {
            uint2 u = *(const uint2*)hp;
            float2 f0 = __half22float2(*(const __half2*)&u.x);
            float2 f1 = __half22float2(*(const __half2*)&u.y);
            acc[0] += f0.x * w; acc[1] += f0.y * w;
            acc[2] += f1.x * w; acc[3] += f1.y * w;
        } else {
            float2 f0 = __half22float2(*(const __half2*)hp);
            acc[0] += f0.x * w; acc[1] += f0.y * w;
        }
    }
    float inv = 1.f / sw;
    const float* ap = agg + (size_t)node * D + lane * V;
    float res[V];
#pragma unroll
    for (int k = 0; k < V; k++) {
        int c = lane * V + k;
        float y = ap[k] * scl[c] + shf[c];   // BN'd residual recomputed inline
        res[k] = lrelu(acc[k] * inv + gb[c] + y);
    }
    if (!OUTH) {
        float* op = (float*)xoutv + (size_t)node * D + lane * V;
        if (V == 4) *(float4*)op = make_float4(res[0], res[1], res[2], res[3]);
        else        *(float2*)op = make_float2(res[0], res[1]);
    } else {
        __half* op = (__half*)xoutv + (size_t)node * D + lane * V;
#pragma unroll
        for (int k = 0; k < V; k += 2)
            *(__half2*)&op[k] = __floats2half2_rn(res[k], res[k + 1]);
    }
}

// ---------------- pooling (BN of last layer fused) ----------------
__global__ void pool_accum_bn_kernel(const float* __restrict__ x, const int* __restrict__ batch,
                                     const float* __restrict__ scl, const float* __restrict__ shf,
                                     float* sums, int Nn, int d) {
    int t = blockIdx.x * blockDim.x + threadIdx.x;
    if (t >= Nn * d) return;
    int n = t / d, c = t % d;
    atomicAdd(&sums[batch[n] * d + c], x[t] * scl[c] + shf[c]);
}

__global__ void pool_cnt_kernel(const int* __restrict__ batch, float* cnt, int Nn) {
    int n = blockIdx.x * blockDim.x + threadIdx.x;
    if (n < Nn) atomicAdd(&cnt[batch[n]], 1.0f);
}

__global__ void pool_final_kernel(const float* __restrict__ sums, const float* __restrict__ cnt,
                                  float* __restrict__ out, int G, int d) {
    int t = blockIdx.x * blockDim.x + threadIdx.x;
    if (t >= G * d) return;
    int g = t / d;
    out[t] = sums[t] / fmaxf(cnt[g], 1.0f);
}

// ---------------- host orchestration ----------------
extern "C" void kernel_launch(void* const* d_in, const int* in_sizes, int n_in,
                              void* d_out, int out_size) {
    const float* x_in  = (const float*)d_in[0];
    const int*   ei    = (const int*)d_in[1];
    const int*   batch = (const int*)d_in[2];
    const float* gcn_w[4], *bn_g[4], *bn_b[4];
    for (int i = 0; i < 4; i++) {
        gcn_w[i] = (const float*)d_in[3 + i * 4 + 0];
        bn_g[i]  = (const float*)d_in[3 + i * 4 + 2];
        bn_b[i]  = (const float*)d_in[3 + i * 4 + 3];
    }
    const float* gat_w[2], *gat_as[2], *gat_ad[2], *gat_b[2];
    for (int j = 0; j < 2; j++) {
        gat_w[j]  = (const float*)d_in[19 + j * 4 + 0];
        gat_as[j] = (const float*)d_in[19 + j * 4 + 1];
        gat_ad[j] = (const float*)d_in[19 + j * 4 + 2];
        gat_b[j]  = (const float*)d_in[19 + j * 4 + 3];
    }
    const int Nn = in_sizes[0] / 16;
    const int E  = in_sizes[1] / 2;
    const int* row = ei;
    const int* col = ei + E;

    float *b0, *b1, *b2, *dis, *asrc, *adst;
    float *bnsum, *bnsq, *scl, *shf, *pool, *cnt;
    int *hist, *off, *cur, *csr_row, *blksum;
    float *csr_nrm;
    cudaGetSymbolAddress((void**)&b0, g_b0);
    cudaGetSymbolAddress((void**)&b1, g_b1);
    cudaGetSymbolAddress((void**)&b2, g_b2);
    cudaGetSymbolAddress((void**)&dis, g_dis);
    cudaGetSymbolAddress((void**)&asrc, g_asrc);
    cudaGetSymbolAddress((void**)&adst, g_adst);
    cudaGetSymbolAddress((void**)&bnsum, g_bnsum);
    cudaGetSymbolAddress((void**)&bnsq, g_bnsq);
    cudaGetSymbolAddress((void**)&scl, g_scale);
    cudaGetSymbolAddress((void**)&shf, g_shift);
    cudaGetSymbolAddress((void**)&pool, g_pool);
    cudaGetSymbolAddress((void**)&cnt, g_cnt);
    cudaGetSymbolAddress((void**)&hist, g_hist);
    cudaGetSymbolAddress((void**)&off, g_off);
    cudaGetSymbolAddress((void**)&cur, g_cur);
    cudaGetSymbolAddress((void**)&csr_row, g_csr_row);
    cudaGetSymbolAddress((void**)&csr_nrm, g_csr_nrm);
    cudaGetSymbolAddress((void**)&blksum, g_blksum);

    // ---- CSR build (by target node), self-loop at segment head ----
    const int nb = cdiv(Nn, SCAN_BLK);
    fill_int_kernel<<<cdiv(Nn, 256), 256>>>(hist, 1, Nn);
    hist_kernel<<<cdiv(E, 256), 256>>>(col, hist, E);
    scan1_kernel<<<nb, SCAN_BLK>>>(hist, blksum, Nn);
    scan2_kernel<<<1, 256>>>(blksum, nb);
    scan3_kernel<<<nb, SCAN_BLK>>>(hist, blksum, off, cur, csr_row, csr_nrm, dis, Nn);
    scatter_kernel<<<cdiv(E, 256), 256>>>(row, col, dis, cur, csr_row, csr_nrm, E);

    const int nodeWarpGrid = cdiv(Nn * 32, 256);
    const float invN = 1.0f / (float)Nn;

    auto clear_stats = [&]() {
        cudaMemsetAsync(bnsum, 0, 128 * sizeof(float));
        cudaMemsetAsync(bnsq, 0, 128 * sizeof(float));
    };
    auto clear_coef = [&]() {
        cudaMemsetAsync(asrc, 0, (size_t)Nn * HEADS * sizeof(float));
        cudaMemsetAsync(adst, 0, (size_t)Nn * HEADS * sizeof(float));
    };

    // ---- layer 0: agg16 (fp32), GEMM(16->64)+stats -> fp32, GAT GEMM -> fp16 hg, GAT ----
    gcn_agg_csr16_kernel<<<nodeWarpGrid, 256>>>(x_in, off, csr_row, csr_nrm, b0, Nn);
    clear_stats();
    gemm_kernel<256, 64, 0, 1, 0><<<dim3(1, cdiv(Nn, 256)), 256>>>(
        b0, gcn_w[0], b1, scl, shf, bnsum, bnsq, nullptr, nullptr, Nn, 64, 16);
    bn_finalize_kernel<<<1, 64>>>(bnsum, bnsq, bn_g[0], bn_b[0], scl, shf, 64, invN);
    clear_coef();
    gemm_kernel<256, 64, 1, 2, 1><<<dim3(1, cdiv(Nn, 256)), 256>>>(
        b1, gat_w[0], (void*)b0, scl, shf, asrc, adst, gat_as[0], gat_ad[0], Nn, 64, 64);
    gat_csr_kernel<64, 1><<<nodeWarpGrid, 256>>>((__half*)b0, asrc, adst, off, csr_row,
                                                 gat_b[0], b1, scl, shf, (void*)b2, Nn);

    // ---- layer 1: agg64 on fp16 x1, GEMM(64->128)+stats ----
    gcn_agg_h_kernel<64, 0><<<nodeWarpGrid, 256>>>((__half*)b2, off, csr_row, csr_nrm,
                                                   b0, nullptr, nullptr, Nn);
    clear_stats();
    gemm_kernel<128, 128, 0, 1, 0><<<dim3(1, cdiv(Nn, 128)), 256>>>(
        b0, gcn_w[1], b1, scl, shf, bnsum, bnsq, nullptr, nullptr, Nn, 128, 64);
    bn_finalize_kernel<<<1, 128>>>(bnsum, bnsq, bn_g[1], bn_b[1], scl, shf, 128, invN);

    // ---- layer 2: GEMM(lrelu(BN) -> 128) fp16 out, agg128+stats, GAT GEMM fp16, GAT ----
    gemm_kernel<128, 128, 2, 0, 1><<<dim3(1, cdiv(Nn, 128)), 256>>>(
        b1, gcn_w[2], (void*)b0, scl, shf, nullptr, nullptr, nullptr, nullptr, Nn, 128, 128);
    clear_stats();
    gcn_agg_h_kernel<128, 1><<<nodeWarpGrid, 256>>>((__half*)b0, off, csr_row, csr_nrm,
                                                    b2, bnsum, bnsq, Nn);
    bn_finalize_kernel<<<1, 128>>>(bnsum, bnsq, bn_g[2], bn_b[2], scl, shf, 128, invN);
    clear_coef();
    gemm_kernel<128, 128, 1, 2, 1><<<dim3(1, cdiv(Nn, 128)), 256>>>(
        b2, gat_w[1], (void*)b0, scl, shf, asrc, adst, gat_as[1], gat_ad[1], Nn, 128, 128);
    gat_csr_kernel<128, 0><<<nodeWarpGrid, 256>>>((__half*)b0, asrc, adst, off, csr_row,
                                                  gat_b[1], b2, scl, shf, (void*)b1, Nn);

    // ---- layer 3: GEMM(128->64) fp16 out, agg64+stats, BN fused into pooling ----
    gemm_kernel<256, 64, 0, 0, 1><<<dim3(1, cdiv(Nn, 256)), 256>>>(
        b1, gcn_w[3], (void*)b2, scl, shf, nullptr, nullptr, nullptr, nullptr, Nn, 64, 128);
    clear_stats();
    gcn_agg_h_kernel<64, 1><<<nodeWarpGrid, 256>>>((__half*)b2, off, csr_row, csr_nrm,
                                                   b0, bnsum, bnsq, Nn);
    bn_finalize_kernel<<<1, 64>>>(bnsum, bnsq, bn_g[3], bn_b[3], scl, shf, 64, invN);

    // ---- global mean pool (BN fused) ----
    const int dfin = 64;
    const int G = out_size / dfin;
    cudaMemsetAsync(pool, 0, (size_t)G * dfin * sizeof(float));
    cudaMemsetAsync(cnt, 0, (size_t)G * sizeof(float));
    pool_accum_bn_kernel<<<cdiv(Nn * dfin, 256), 256>>>(b0, batch, scl, shf, pool, Nn, dfin);
    pool_cnt_kernel<<<cdiv(Nn, 256), 256>>>(batch, cnt, Nn);
    pool_final_kernel<<<cdiv(G * dfin, 256), 256>>>(pool, cnt, (float*)d_out, G, dfin);
}